// round 6
// baseline (speedup 1.0000x reference)
#include <cuda_runtime.h>
#include <cstdint>

#define BB    64
#define SS    1024
#define HH    1000
#define SPLIT 16
#define CHUNK (SS / SPLIT)    /* 64 rows per CTA */
#define WPB   4               /* warps per block */
#define RPW   (CHUNK / WPB)   /* 16 rows per warp */
#define H4    250             /* float4 per row */

#define NGS   16
#define GPS   63

// Scratch (static device arrays: allocation-free per harness rules)
__device__ float g_vp[NGS * BB * HH];        // 4 MB   v partials
__device__ float g_v[BB * HH];               // 256 KB v = h_tgt @ W
__device__ float g_part[SPLIT * BB * HH];    // 4 MB   unnormalized acc per split
__device__ float g_ml[SPLIT * BB * 2];       // (m, l) per split

// ---------------------------------------------------------------------------
// Kernel 1: v partials.  grid (16 h-chunks, 16 g-splits), 256 threads.
// ---------------------------------------------------------------------------
__global__ __launch_bounds__(256) void v_partial_kernel(
    const float* __restrict__ h_tgt, const float* __restrict__ Wm)
{
    __shared__ float stg[64 * GPS];
    const int hb = blockIdx.x, gs = blockIdx.y;
    const int h0 = hb * 64, g0 = gs * GPS;
    const int gcnt = min(GPS, HH - g0);
    const int t = threadIdx.x;

    for (int idx = t; idx < 64 * GPS; idx += 256) {
        int b  = idx / GPS;
        int gi = idx - b * GPS;
        int g  = g0 + gi;
        stg[idx] = (g < HH) ? h_tgt[b * HH + g] : 0.f;
    }
    __syncthreads();

    const int hq = t & 15, bg = t >> 4;
    const int h  = h0 + hq * 4;
    if ((h + 3) < HH) {
        float4 acc[4];
        #pragma unroll
        for (int i = 0; i < 4; i++) acc[i] = make_float4(0.f, 0.f, 0.f, 0.f);

        for (int gi = 0; gi < gcnt; gi++) {
            float4 w4 = __ldg((const float4*)(Wm + (size_t)(g0 + gi) * HH + h));
            #pragma unroll
            for (int bb = 0; bb < 4; bb++) {
                float tb = stg[(bg * 4 + bb) * GPS + gi];
                acc[bb].x += tb * w4.x;
                acc[bb].y += tb * w4.y;
                acc[bb].z += tb * w4.z;
                acc[bb].w += tb * w4.w;
            }
        }
        #pragma unroll
        for (int bb = 0; bb < 4; bb++) {
            int b = bg * 4 + bb;
            *((float4*)(g_vp + (size_t)gs * (BB * HH) + b * HH + h)) = acc[bb];
        }
    }
}

// ---------------------------------------------------------------------------
// Kernel 2: reduce v partials.
// ---------------------------------------------------------------------------
__global__ __launch_bounds__(256) void v_reduce_kernel()
{
    int i = blockIdx.x * 256 + threadIdx.x;
    float s = 0.f;
    #pragma unroll
    for (int gs = 0; gs < NGS; gs++) s += g_vp[gs * (BB * HH) + i];
    g_v[i] = s;
}

// ---------------------------------------------------------------------------
// Kernel 3: warp-autonomous streaming attention. NO mainloop barriers.
// Each warp: 16 contiguous rows, GMEM->regs double-buffered, score+accum
// from the SAME registers. v read from SMEM (conflict-free LDS.128).
// ---------------------------------------------------------------------------
__device__ __forceinline__ void load_row(float4 (&buf)[8],
                                         const float4* __restrict__ p, int lane)
{
    #pragma unroll
    for (int j = 0; j < 7; j++) buf[j] = p[lane + 32 * j];
    buf[7] = make_float4(0.f, 0.f, 0.f, 0.f);
    if (lane < 26) buf[7] = p[224 + lane];
}

__device__ __forceinline__ void process_row(const float4 (&a)[8],
                                            const float4* __restrict__ v4,
                                            int lane, float& m, float& l,
                                            float4 (&acc)[8])
{
    float s0 = 0.f, s1 = 0.f, s2 = 0.f, s3 = 0.f;
    #pragma unroll
    for (int j = 0; j < 7; j++) {
        float4 v = v4[lane + 32 * j];
        s0 += a[j].x * v.x; s1 += a[j].y * v.y;
        s2 += a[j].z * v.z; s3 += a[j].w * v.w;
    }
    if (lane < 26) {
        float4 v = v4[224 + lane];
        s0 += a[7].x * v.x; s1 += a[7].y * v.y;
        s2 += a[7].z * v.z; s3 += a[7].w * v.w;
    }
    float s = (s0 + s1) + (s2 + s3);
    #pragma unroll
    for (int o = 16; o; o >>= 1) s += __shfl_xor_sync(0xffffffffu, s, o);

    float nm   = fmaxf(m, s);
    float corr = __expf(m - nm);
    float p    = __expf(s - nm);
    m = nm;
    l = l * corr + p;
    #pragma unroll
    for (int j = 0; j < 8; j++) {
        acc[j].x = acc[j].x * corr + p * a[j].x;
        acc[j].y = acc[j].y * corr + p * a[j].y;
        acc[j].z = acc[j].z * corr + p * a[j].z;
        acc[j].w = acc[j].w * corr + p * a[j].w;
    }
}

__global__ __launch_bounds__(128) void attn_main_kernel(const float* __restrict__ h_src)
{
    __shared__ float  sv[1024];          // v for this batch (4 KB)
    __shared__ float4 sacc[WPB][256];    // per-warp acc partials (16 KB)
    __shared__ float  sml[WPB][2];

    const int sp = blockIdx.x, b = blockIdx.y;
    const int t = threadIdx.x, lane = t & 31, w = t >> 5;

    // Warp's contiguous row range start
    const float4* rp = (const float4*)(h_src +
        ((size_t)b * SS + (size_t)sp * CHUNK + (size_t)w * RPW) * HH);

    float4 A[8], B[8];
    load_row(A, rp, lane);               // row 0 in flight before sv barrier

    for (int i = t; i < HH; i += 128) sv[i] = g_v[b * HH + i];
    __syncthreads();
    const float4* v4 = (const float4*)sv;

    float m = -1e30f, l = 0.f;
    float4 acc[8];
    #pragma unroll
    for (int j = 0; j < 8; j++) acc[j] = make_float4(0.f, 0.f, 0.f, 0.f);

    #pragma unroll 1
    for (int i = 0; i < RPW; i += 2) {
        load_row(B, rp + H4, lane);                       // row i+1 (always exists)
        process_row(A, v4, lane, m, l, acc);              // row i
        if (i + 2 < RPW) load_row(A, rp + 2 * H4, lane);  // row i+2
        process_row(B, v4, lane, m, l, acc);              // row i+1
        rp += 2 * H4;
    }

    // Merge 4 warp partials within CTA
    #pragma unroll
    for (int j = 0; j < 8; j++) sacc[w][lane + 32 * j] = acc[j];
    if (lane == 0) { sml[w][0] = m; sml[w][1] = l; }
    __syncthreads();

    float M = fmaxf(fmaxf(sml[0][0], sml[1][0]), fmaxf(sml[2][0], sml[3][0]));
    float wgt[WPB];
    float L = 0.f;
    #pragma unroll
    for (int i = 0; i < WPB; i++) {
        wgt[i] = __expf(sml[i][0] - M);
        L += sml[i][1] * wgt[i];
    }

    float4* dst = (float4*)(g_part + (size_t)(sp * BB + b) * HH);
    #pragma unroll
    for (int rep = 0; rep < 2; rep++) {
        int slot = t + rep * 128;
        if (slot < H4) {
            float4 o = make_float4(0.f, 0.f, 0.f, 0.f);
            #pragma unroll
            for (int i = 0; i < WPB; i++) {
                float4 x = sacc[i][slot];
                o.x += wgt[i] * x.x; o.y += wgt[i] * x.y;
                o.z += wgt[i] * x.z; o.w += wgt[i] * x.w;
            }
            dst[slot] = o;
        }
    }
    if (t == 0) {
        g_ml[(sp * BB + b) * 2]     = M;
        g_ml[(sp * BB + b) * 2 + 1] = L;
    }
}

// ---------------------------------------------------------------------------
// Kernel 4: combine SPLIT partials (log-sum-exp merge) -> output.
// grid (BB, 2) x 128 threads.
// ---------------------------------------------------------------------------
__global__ __launch_bounds__(128) void combine_kernel(float* __restrict__ out)
{
    const int b = blockIdx.x;
    const int slot = blockIdx.y * 128 + threadIdx.x;

    float mv[SPLIT], lv[SPLIT];
    #pragma unroll
    for (int i = 0; i < SPLIT; i++) {
        mv[i] = g_ml[(i * BB + b) * 2];
        lv[i] = g_ml[(i * BB + b) * 2 + 1];
    }
    float M = mv[0];
    #pragma unroll
    for (int i = 1; i < SPLIT; i++) M = fmaxf(M, mv[i]);
    float w[SPLIT];
    float L = 0.f;
    #pragma unroll
    for (int i = 0; i < SPLIT; i++) { w[i] = __expf(mv[i] - M); L += lv[i] * w[i]; }
    const float inv = 1.f / L;

    if (slot < H4) {
        float4 o = make_float4(0.f, 0.f, 0.f, 0.f);
        #pragma unroll
        for (int i = 0; i < SPLIT; i++) {
            float4 x = *((const float4*)(g_part + (size_t)(i * BB + b) * HH) + slot);
            o.x += w[i] * x.x; o.y += w[i] * x.y;
            o.z += w[i] * x.z; o.w += w[i] * x.w;
        }
        o.x *= inv; o.y *= inv; o.z *= inv; o.w *= inv;
        *((float4*)(out + (size_t)b * HH) + slot) = o;
    }
}

// ---------------------------------------------------------------------------
extern "C" void kernel_launch(void* const* d_in, const int* in_sizes, int n_in,
                              void* d_out, int out_size)
{
    const float* h_tgt = (const float*)d_in[0];   // [64, 1, 1000]
    const float* h_src = (const float*)d_in[1];   // [64, 1024, 1000]
    const float* Wm    = (const float*)d_in[2];   // [1000, 1000]
    // d_in[3] = bias: cancels under softmax shift-invariance; unused.
    float* out = (float*)d_out;                   // [64, 1, 1000]

    v_partial_kernel<<<dim3(16, NGS), 256>>>(h_tgt, Wm);
    v_reduce_kernel<<<(BB * HH) / 256, 256>>>();
    attn_main_kernel<<<dim3(SPLIT, BB), 128>>>(h_src);
    combine_kernel<<<dim3(BB, 2), 128>>>(out);
}